// round 2
// baseline (speedup 1.0000x reference)
#include <cuda_runtime.h>

// Problem constants
#define NPTS 1048576
#define BSEG 2048
#define NFEAT 64
#define NENC 32

// Shared memory layout (in floats):
//  [0,8192)        W1f  : w1 rows 32..95   [64][128]
//  [8192,24576)    W2   : [128][128]
//  [24576,40960)   W3   : [128][128]
//  [40960,49152)   buf0 : 32KB activation buffer (also aliased for pass-1 misc and g-phase)
//  [49152,57344)   buf1 : 32KB activation buffer
//  [57344,57472)   seg_part[128]
//  [57472,57600)   pooled[128] (int bits, nonneg-float max)
//  [57600,57728)   b2s[128]
//  [57728,57856)   b3s[128]
#define SMEM_FLOATS 57856
#define SMEM_BYTES (SMEM_FLOATS * 4)   // 231424 < 232448 limit

__device__ __forceinline__ void fma4(float4& c, const float4 a, const float s) {
    c.x += a.x * s; c.y += a.y * s; c.z += a.z * s; c.w += a.w * s;
}

template<int K>
__device__ __forceinline__ void gemm_layer(const float* __restrict__ Ws,
                                           const float* __restrict__ in,
                                           float4 acc[8], int tp4, int to8)
{
#pragma unroll 4
    for (int k = 0; k < K; k++) {
        float4 a  = *(const float4*)(in + k * 64 + tp4);
        float4 bA = *(const float4*)(Ws + k * 128 + to8);
        float4 bB = *(const float4*)(Ws + k * 128 + to8 + 4);
        fma4(acc[0], a, bA.x); fma4(acc[1], a, bA.y);
        fma4(acc[2], a, bA.z); fma4(acc[3], a, bA.w);
        fma4(acc[4], a, bB.x); fma4(acc[5], a, bB.y);
        fma4(acc[6], a, bB.z); fma4(acc[7], a, bB.w);
    }
}

__device__ __forceinline__ void store_relu(float* __restrict__ outb,
                                           float4 acc[8], int tp4, int to8)
{
#pragma unroll
    for (int j = 0; j < 8; j++) {
        float4 r;
        r.x = fmaxf(acc[j].x, 0.f); r.y = fmaxf(acc[j].y, 0.f);
        r.z = fmaxf(acc[j].z, 0.f); r.w = fmaxf(acc[j].w, 0.f);
        *(float4*)(outb + (to8 + j) * 64 + tp4) = r;
    }
}

__global__ void __launch_bounds__(256, 1)
inside_encoder_kernel(const float* __restrict__ points,
                      const float* __restrict__ features,
                      const int*   __restrict__ batch_words,   // int32 or int64 (detected)
                      const float* __restrict__ w_ne, const float* __restrict__ b_ne,
                      const float* __restrict__ w1,   const float* __restrict__ b1,
                      const float* __restrict__ w2,   const float* __restrict__ b2,
                      const float* __restrict__ w3,   const float* __restrict__ b3,
                      const float* __restrict__ wg1,  const float* __restrict__ bg1,
                      const float* __restrict__ wg2,  const float* __restrict__ bg2,
                      const float* __restrict__ wg3,  const float* __restrict__ bg3,
                      float* __restrict__ out)
{
    extern __shared__ float smem[];
    float* W1f      = smem;
    float* W2s      = smem + 8192;
    float* W3s      = smem + 24576;
    float* buf0     = smem + 40960;
    float* buf1     = smem + 49152;
    float* seg_part = smem + 57344;
    int*   pooled   = (int*)(smem + 57472);
    float* b2s      = smem + 57600;
    float* b3s      = smem + 57728;
    // pass-1 aliases inside buf0
    float* wne      = buf0;            // 96
    float* bne      = buf0 + 96;       // 32
    float* wpart    = buf0 + 128;      // 8*32
    float* seg_enc  = buf0 + 384;      // 32
    // g-phase aliases inside buf0
    float* g1s      = buf0;            // 128
    float* g2s      = buf0 + 128;      // 64

    const int b   = blockIdx.x;
    const int tid = threadIdx.x;

    // ---- batch dtype detection: int64 -> word[N-1] is a high word == 0;
    //      int32 -> word[N-1] = last batch id (~2047, >0 w.p. ~1).
    const int stride = (batch_words[NPTS - 1] == 0) ? 2 : 1;

    // ---- binary search segment bounds [lo, hi)
    int lo, hi;
    {
        int l = 0, h = NPTS;
        while (l < h) { int m = (l + h) >> 1; if (batch_words[m * stride] < b) l = m + 1; else h = m; }
        lo = l;
        h = NPTS;
        while (l < h) { int m = (l + h) >> 1; if (batch_words[m * stride] < b + 1) l = m + 1; else h = m; }
        hi = l;
    }

    // ---- stage weights into smem
    for (int i = tid; i < 8192;  i += 256) W1f[i] = w1[4096 + i];   // rows 32..95
    for (int i = tid; i < 16384; i += 256) W2s[i] = w2[i];
    for (int i = tid; i < 16384; i += 256) W3s[i] = w3[i];
    if (tid < 128) { b2s[tid] = b2[tid]; b3s[tid] = b3[tid]; pooled[tid] = 0; }
    if (tid < 96)  wne[tid] = w_ne[tid];
    if (tid < 32)  bne[tid] = b_ne[tid];
    __syncthreads();

    // ---- pass 1: neighborhood encoder + segment max (relu>=0, 0 is identity)
    float em[NENC];
#pragma unroll
    for (int j = 0; j < NENC; j++) em[j] = 0.f;
    for (int n = lo + tid; n < hi; n += 256) {
        float x = points[3 * n], y = points[3 * n + 1], z = points[3 * n + 2];
#pragma unroll
        for (int j = 0; j < NENC; j++) {
            float e = bne[j] + x * wne[j] + y * wne[32 + j] + z * wne[64 + j];
            em[j] = fmaxf(em[j], e);
        }
    }
#pragma unroll
    for (int j = 0; j < NENC; j++) {
#pragma unroll
        for (int o = 16; o > 0; o >>= 1)
            em[j] = fmaxf(em[j], __shfl_xor_sync(0xFFFFFFFFu, em[j], o));
    }
    const int warp = tid >> 5, lane = tid & 31;
    if (lane == 0) {
#pragma unroll
        for (int j = 0; j < NENC; j++) wpart[warp * 32 + j] = em[j];
    }
    __syncthreads();
    if (tid < 32) {
        float m = wpart[tid];
#pragma unroll
        for (int w = 1; w < 8; w++) m = fmaxf(m, wpart[w * 32 + tid]);
        seg_enc[tid] = m;
    }
    __syncthreads();
    // seg_part = seg_enc @ w1[0:32] + b1  (w1 top rows streamed from L2)
    if (tid < 128) {
        float s = b1[tid];
#pragma unroll
        for (int k = 0; k < 32; k++) s += seg_enc[k] * w1[k * 128 + tid];
        seg_part[tid] = s;
    }

    // ---- pass 2: per-point 3-layer MLP (tiles of 64 points), running max into regs
    const int tp4 = (tid & 15) * 4;
    const int to8 = (tid >> 4) * 8;
    float runmax[8];
#pragma unroll
    for (int j = 0; j < 8; j++) runmax[j] = 0.f;

    for (int base = lo; base < hi; base += 64) {
        __syncthreads();   // protect buf0 (prev tile L3 reads / pass-1 aliases)
        {
            const int kq   = tid & 15;
            const int prow = tid >> 4;
#pragma unroll
            for (int r = 0; r < 4; r++) {
                int p = r * 16 + prow;
                int n = base + p;
                float4 v = make_float4(0.f, 0.f, 0.f, 0.f);
                if (n < hi) v = ((const float4*)features)[(size_t)n * 16 + kq];
                buf0[(4 * kq + 0) * 64 + p] = v.x;
                buf0[(4 * kq + 1) * 64 + p] = v.y;
                buf0[(4 * kq + 2) * 64 + p] = v.z;
                buf0[(4 * kq + 3) * 64 + p] = v.w;
            }
        }
        __syncthreads();

        float4 acc[8];
        // layer 1: K=64, bias = seg_part (includes enc contribution + b1)
#pragma unroll
        for (int j = 0; j < 8; j++) { float s = seg_part[to8 + j]; acc[j] = make_float4(s, s, s, s); }
        gemm_layer<64>(W1f, buf0, acc, tp4, to8);
        store_relu(buf1, acc, tp4, to8);
        __syncthreads();

        // layer 2: K=128
#pragma unroll
        for (int j = 0; j < 8; j++) { float s = b2s[to8 + j]; acc[j] = make_float4(s, s, s, s); }
        gemm_layer<128>(W2s, buf1, acc, tp4, to8);
        store_relu(buf0, acc, tp4, to8);
        __syncthreads();

        // layer 3: K=128, output stays in regs -> masked running max (relu folded: runmax>=0)
#pragma unroll
        for (int j = 0; j < 8; j++) { float s = b3s[to8 + j]; acc[j] = make_float4(s, s, s, s); }
        gemm_layer<128>(W3s, buf0, acc, tp4, to8);

        const int rem = hi - base;   // valid points in this tile
#pragma unroll
        for (int j = 0; j < 8; j++) {
            if (tp4 + 0 < rem) runmax[j] = fmaxf(runmax[j], acc[j].x);
            if (tp4 + 1 < rem) runmax[j] = fmaxf(runmax[j], acc[j].y);
            if (tp4 + 2 < rem) runmax[j] = fmaxf(runmax[j], acc[j].z);
            if (tp4 + 3 < rem) runmax[j] = fmaxf(runmax[j], acc[j].w);
        }
    }

    // reduce running max into pooled (nonneg floats: int compare == float compare)
#pragma unroll
    for (int j = 0; j < 8; j++)
        atomicMax(&pooled[to8 + j], __float_as_int(runmax[j]));
    __syncthreads();

    // ---- pass 3: per-segment head MLP 128 -> 128 -> 64 -> 32
    if (tid < 128) {
        float s = bg1[tid];
#pragma unroll 8
        for (int k = 0; k < 128; k++) s += __int_as_float(pooled[k]) * wg1[k * 128 + tid];
        g1s[tid] = fmaxf(s, 0.f);
    }
    __syncthreads();
    if (tid < 64) {
        float s = bg2[tid];
#pragma unroll 8
        for (int k = 0; k < 128; k++) s += g1s[k] * wg2[k * 64 + tid];
        g2s[tid] = fmaxf(s, 0.f);
    }
    __syncthreads();
    if (tid < 32) {
        float s = bg3[tid];
#pragma unroll 8
        for (int k = 0; k < 64; k++) s += g2s[k] * wg3[k * 32 + tid];
        out[b * 32 + tid] = fmaxf(s, 0.f);
    }
}

extern "C" void kernel_launch(void* const* d_in, const int* in_sizes, int n_in,
                              void* d_out, int out_size)
{
    const float* points   = (const float*)d_in[0];
    const float* features = (const float*)d_in[1];
    const int*   batchw   = (const int*)  d_in[2];   // int32 or int64, detected on device
    const float* w_ne = (const float*)d_in[3];
    const float* b_ne = (const float*)d_in[4];
    const float* w1   = (const float*)d_in[5];
    const float* b1   = (const float*)d_in[6];
    const float* w2   = (const float*)d_in[7];
    const float* b2   = (const float*)d_in[8];
    const float* w3   = (const float*)d_in[9];
    const float* b3   = (const float*)d_in[10];
    const float* wg1  = (const float*)d_in[11];
    const float* bg1  = (const float*)d_in[12];
    const float* wg2  = (const float*)d_in[13];
    const float* bg2  = (const float*)d_in[14];
    const float* wg3  = (const float*)d_in[15];
    const float* bg3  = (const float*)d_in[16];
    float* out = (float*)d_out;

    cudaFuncSetAttribute(inside_encoder_kernel,
                         cudaFuncAttributeMaxDynamicSharedMemorySize, SMEM_BYTES);
    inside_encoder_kernel<<<BSEG, 256, SMEM_BYTES>>>(
        points, features, batchw,
        w_ne, b_ne, w1, b1, w2, b2, w3, b3,
        wg1, bg1, wg2, bg2, wg3, bg3, out);
}

// round 4
// speedup vs baseline: 1.0211x; 1.0211x over previous
#include <cuda_runtime.h>
#include <cstdint>

#define NPTS 1048576
#define BSEG 2048
#define NCTA 148

// smem layout (float offsets); pads hold biases/seg_part/pooled
//  W1f : [0, 8448)      rows stride 66 ; [o*66+k] k<64 ; hole: +64 = seg_part[o], +65 = pooled[o] (int bits)
//  W2  : [8448, 25088)  rows stride 130; hole +128 = b2[o]
//  W3  : [25088, 41728) rows stride 130; hole +128 = b3[o]
//  bufA: [41728, 49920) 64 rows x 128  (L1-in cols 0..63, L2-out/L3-in; pass-1 & head scratch)
//  bufB: [49920, 58112) 64 rows x 128  (L1-out/L2-in; head scratch g1/g2)
#define F_W1  0
#define F_W2  8448
#define F_W3  25088
#define F_BA  41728
#define F_BB  49920
#define SMEM_FLOATS 58112
#define SMEM_BYTES (SMEM_FLOATS * 4)   // 232448 == max opt-in dynamic smem

typedef unsigned long long u64;

__device__ __forceinline__ void ffma2(u64& c, u64 a, u64 b) {
    asm("fma.rn.f32x2 %0, %1, %2, %0;" : "+l"(c) : "l"(a), "l"(b));
}
__device__ __forceinline__ float acc_sum(u64 c) {
    return __uint_as_float((unsigned)c) + __uint_as_float((unsigned)(c >> 32));
}

// 4 points x 8 outs, k-pair-packed f32x2 GEMM core.
// a0: this thread's first act row; w0: weight row of out og (outs og+16j).
template<int KHALF, int WSTR>
__device__ __forceinline__ void gemm_tile(const float* __restrict__ a0,
                                          const float* __restrict__ w0,
                                          u64 acc[4][8])
{
#pragma unroll 4
    for (int t = 0; t < KHALF; t++) {
        u64 av[4], bv[8];
#pragma unroll
        for (int i = 0; i < 4; i++)
            av[i] = *(const u64*)(a0 + i * 128 + 2 * t);
#pragma unroll
        for (int j = 0; j < 8; j++)
            bv[j] = *(const u64*)(w0 + j * 16 * WSTR + 2 * t);
#pragma unroll
        for (int i = 0; i < 4; i++)
#pragma unroll
            for (int j = 0; j < 8; j++)
                ffma2(acc[i][j], av[i], bv[j]);
    }
}

__global__ void __launch_bounds__(256, 1)
enc_kernel(const float* __restrict__ points, const float* __restrict__ features,
           const int* __restrict__ batch_words,
           const float* __restrict__ w_ne, const float* __restrict__ b_ne,
           const float* __restrict__ w1, const float* __restrict__ b1,
           const float* __restrict__ w2, const float* __restrict__ b2,
           const float* __restrict__ w3, const float* __restrict__ b3,
           const float* __restrict__ wg1, const float* __restrict__ bg1,
           const float* __restrict__ wg2, const float* __restrict__ bg2,
           const float* __restrict__ wg3, const float* __restrict__ bg3,
           float* __restrict__ out)
{
    extern __shared__ float sm[];
    float* sW1  = sm + F_W1;
    float* sW2  = sm + F_W2;
    float* sW3  = sm + F_W3;
    float* bufA = sm + F_BA;
    float* bufB = sm + F_BB;

    const int tid  = threadIdx.x;
    const int lane = tid & 31, w = tid >> 5;
    const int og   = lane & 15, phh = lane >> 4;

    // ---- stage weights (transposed, padded rows), biases into pad holes ----
    for (int idx = tid; idx < 8192; idx += 256) {            // W1 rows 32..95
        int o = idx & 127, k = idx >> 7;
        sW1[o * 66 + k] = w1[(32 + k) * 128 + o];
    }
    for (int idx = tid; idx < 16384; idx += 256) {
        int o = idx & 127, k = idx >> 7;
        sW2[o * 130 + k] = w2[k * 128 + o];
        sW3[o * 130 + k] = w3[k * 128 + o];
    }
    if (tid < 128) {
        sW2[tid * 130 + 128] = b2[tid];
        sW3[tid * 130 + 128] = b3[tid];
    }
    __syncthreads();

    // batch dtype detection (int64 -> high word at [N-1] is 0)
    const int stride = (batch_words[NPTS - 1] == 0) ? 2 : 1;

    // warp-private act rows
    float* rowA = bufA + (w * 8 + phh * 4) * 128;
    float* rowB = bufB + (w * 8 + phh * 4) * 128;
    const float* w1p = sW1 + og * 66;
    const float* w2p = sW2 + og * 130;
    const float* w3p = sW3 + og * 130;

    const int s0 = (blockIdx.x * BSEG) / NCTA;
    const int s1 = ((blockIdx.x + 1) * BSEG) / NCTA;

    for (int b = s0; b < s1; b++) {
        // ---- segment bounds (batch sorted) ----
        int lo, hi;
        {
            int l = 0, h = NPTS;
            while (l < h) { int m = (l + h) >> 1; if (batch_words[m * stride] < b) l = m + 1; else h = m; }
            lo = l; h = NPTS;
            while (l < h) { int m = (l + h) >> 1; if (batch_words[m * stride] < b + 1) l = m + 1; else h = m; }
            hi = l;
        }

        // ---- pass 1: encoder + segment max -> seg_part (in W1 pad holes) ----
        if (tid < 128) ((int*)sW1)[tid * 66 + 65] = 0;       // pooled reset
        if (tid < 96)  bufA[tid] = w_ne[tid];
        if (tid < 32)  bufA[96 + tid] = b_ne[tid];
        __syncthreads();
        {
            float em[32];
#pragma unroll
            for (int j = 0; j < 32; j++) em[j] = 0.f;
            const float* wne = bufA; const float* bne = bufA + 96;
            for (int n = lo + tid; n < hi; n += 256) {
                float x = points[3 * n], y = points[3 * n + 1], z = points[3 * n + 2];
#pragma unroll
                for (int j = 0; j < 32; j++)
                    em[j] = fmaxf(em[j], bne[j] + x * wne[j] + y * wne[32 + j] + z * wne[64 + j]);
            }
#pragma unroll
            for (int j = 0; j < 32; j++) {
#pragma unroll
                for (int o = 16; o > 0; o >>= 1)
                    em[j] = fmaxf(em[j], __shfl_xor_sync(0xFFFFFFFFu, em[j], o));
            }
            if (lane == 0) {
#pragma unroll
                for (int j = 0; j < 32; j++) bufA[128 + w * 32 + j] = em[j];
            }
            __syncthreads();
            if (tid < 32) {
                float m = bufA[128 + tid];
#pragma unroll
                for (int q = 1; q < 8; q++) m = fmaxf(m, bufA[128 + q * 32 + tid]);
                bufA[384 + tid] = m;                          // seg_enc
            }
            __syncthreads();
            if (tid < 128) {
                float s = b1[tid];
#pragma unroll
                for (int k = 0; k < 32; k++) s += bufA[384 + k] * w1[k * 128 + tid];
                sW1[tid * 66 + 64] = s;                       // seg_part hole
            }
            __syncthreads();
        }

        // ---- pass 2: warp-private 8-point chunks through the 3-layer MLP ----
        float rm[8];
#pragma unroll
        for (int j = 0; j < 8; j++) rm[j] = 0.f;

        float4 f[4];
        int n0 = lo + w * 8;
#pragma unroll
        for (int i = 0; i < 4; i++) {                         // preload chunk 0
            int n = n0 + phh * 4 + i;
            f[i] = (n < hi) ? ((const float4*)features)[(size_t)n * 16 + og]
                            : make_float4(0.f, 0.f, 0.f, 0.f);
        }

        for (; n0 < hi; n0 += 64) {
            // stage features (L1 A operand, cols 0..63 of rowA)
#pragma unroll
            for (int i = 0; i < 4; i++)
                *(float4*)(rowA + i * 128 + og * 4) = f[i];
            __syncwarp();
            // prefetch next chunk during GEMMs
            {
                int nn = n0 + 64;
#pragma unroll
                for (int i = 0; i < 4; i++) {
                    int n = nn + phh * 4 + i;
                    f[i] = (n < hi) ? ((const float4*)features)[(size_t)n * 16 + og]
                                    : make_float4(0.f, 0.f, 0.f, 0.f);
                }
            }

            u64 acc[4][8];
            // layer 1 (K=64), bias = seg_part
#pragma unroll
            for (int j = 0; j < 8; j++) {
                u64 c = (u64)__float_as_uint(sW1[(og + 16 * j) * 66 + 64]);
#pragma unroll
                for (int i = 0; i < 4; i++) acc[i][j] = c;
            }
            gemm_tile<32, 66>(rowA, w1p, acc);
#pragma unroll
            for (int i = 0; i < 4; i++)
#pragma unroll
                for (int j = 0; j < 8; j++)
                    rowB[i * 128 + og + 16 * j] = fmaxf(acc_sum(acc[i][j]), 0.f);
            __syncwarp();

            // layer 2 (K=128), bias = b2 (hole)
#pragma unroll
            for (int j = 0; j < 8; j++) {
                u64 c = (u64)__float_as_uint(sW2[(og + 16 * j) * 130 + 128]);
#pragma unroll
                for (int i = 0; i < 4; i++) acc[i][j] = c;
            }
            gemm_tile<64, 130>(rowB, w2p, acc);
#pragma unroll
            for (int i = 0; i < 4; i++)
#pragma unroll
                for (int j = 0; j < 8; j++)
                    rowA[i * 128 + og + 16 * j] = fmaxf(acc_sum(acc[i][j]), 0.f);
            __syncwarp();

            // layer 3 (K=128), bias = b3; relu folded into max-with-0
#pragma unroll
            for (int j = 0; j < 8; j++) {
                u64 c = (u64)__float_as_uint(sW3[(og + 16 * j) * 130 + 128]);
#pragma unroll
                for (int i = 0; i < 4; i++) acc[i][j] = c;
            }
            gemm_tile<64, 130>(rowA, w3p, acc);
#pragma unroll
            for (int i = 0; i < 4; i++) {
                bool valid = (n0 + phh * 4 + i) < hi;
                if (valid) {
#pragma unroll
                    for (int j = 0; j < 8; j++)
                        rm[j] = fmaxf(rm[j], acc_sum(acc[i][j]));
                }
            }
            __syncwarp();
        }

        // combine ph halves, then shared atomics into pooled holes
#pragma unroll
        for (int j = 0; j < 8; j++)
            rm[j] = fmaxf(rm[j], __shfl_xor_sync(0xFFFFFFFFu, rm[j], 16));
        if (phh == 0) {
#pragma unroll
            for (int j = 0; j < 8; j++)
                atomicMax(&((int*)sW1)[(og + 16 * j) * 66 + 65], __float_as_int(rm[j]));
        }
        __syncthreads();

        // ---- pass 3: head MLP 128 -> 128 -> 64 -> 32 (bufB scratch) ----
        if (tid < 128) {
            float s = bg1[tid];
#pragma unroll 8
            for (int k = 0; k < 128; k++)
                s += __int_as_float(((int*)sW1)[k * 66 + 65]) * wg1[k * 128 + tid];
            bufB[tid] = fmaxf(s, 0.f);
        }
        __syncthreads();
        if (tid < 64) {
            float s = bg2[tid];
#pragma unroll 8
            for (int k = 0; k < 128; k++) s += bufB[k] * wg2[k * 64 + tid];
            bufB[128 + tid] = fmaxf(s, 0.f);
        }
        __syncthreads();
        if (tid < 32) {
            float s = bg3[tid];
#pragma unroll 8
            for (int k = 0; k < 64; k++) s += bufB[128 + k] * wg3[k * 32 + tid];
            out[b * 32 + tid] = fmaxf(s, 0.f);
        }
        __syncthreads();
    }
}

extern "C" void kernel_launch(void* const* d_in, const int* in_sizes, int n_in,
                              void* d_out, int out_size)
{
    const float* points   = (const float*)d_in[0];
    const float* features = (const float*)d_in[1];
    const int*   batchw   = (const int*)  d_in[2];
    const float* w_ne = (const float*)d_in[3];
    const float* b_ne = (const float*)d_in[4];
    const float* w1   = (const float*)d_in[5];
    const float* b1   = (const float*)d_in[6];
    const float* w2   = (const float*)d_in[7];
    const float* b2   = (const float*)d_in[8];
    const float* w3   = (const float*)d_in[9];
    const float* b3   = (const float*)d_in[10];
    const float* wg1  = (const float*)d_in[11];
    const float* bg1  = (const float*)d_in[12];
    const float* wg2  = (const float*)d_in[13];
    const float* bg2  = (const float*)d_in[14];
    const float* wg3  = (const float*)d_in[15];
    const float* bg3  = (const float*)d_in[16];
    float* out = (float*)d_out;

    cudaFuncSetAttribute(enc_kernel, cudaFuncAttributeMaxDynamicSharedMemorySize, SMEM_BYTES);
    enc_kernel<<<NCTA, 256, SMEM_BYTES>>>(
        points, features, batchw,
        w_ne, b_ne, w1, b1, w2, b2, w3, b3,
        wg1, bg1, wg2, bg2, wg3, bg3, out);
}

// round 7
// speedup vs baseline: 2.2374x; 2.1912x over previous
#include <cuda_runtime.h>
#include <cuda_fp16.h>
#include <cstdint>

#define NPTS 1048576
#define BSEG 2048
#define NCTA 148

// smem byte offsets
//  W1H/W1L: [128 o][64 k] fp16, SW128 rows (16KB each)
//  W2H/W2L, W3H/W3L: 2 k-blocks of [128 o][64 k] (32KB each)
//  ACT: 2 buffers x (H 16KB + L 16KB); each H/L = 2 k-blocks of [64 pt][64 k]
#define O_W1H 0
#define O_W1L 16384
#define O_W2H 32768
#define O_W2L 65536
#define O_W3H 98304
#define O_W3L 131072
#define O_ACT 163840
#define O_SEGP 229376
#define O_POOL 229888
#define O_B2   230400
#define O_B3   230912
#define SMEM_BYTES 231424

#define SWZ(x) ((uint32_t)(x) ^ ((((uint32_t)(x)) >> 3) & 0x70))

__device__ __forceinline__ uint32_t smem_u32(const void* p) {
    uint32_t a;
    asm("{ .reg .u64 t; cvta.to.shared.u64 t, %1; cvt.u32.u64 %0, t; }" : "=r"(a) : "l"(p));
    return a;
}
__device__ __forceinline__ void ldsm_x4(uint32_t addr, uint32_t r[4]) {
    asm volatile("ldmatrix.sync.aligned.m8n8.x4.shared.b16 {%0,%1,%2,%3}, [%4];"
        : "=r"(r[0]), "=r"(r[1]), "=r"(r[2]), "=r"(r[3]) : "r"(addr));
}
__device__ __forceinline__ void ldsm_x2(uint32_t addr, uint32_t r[2]) {
    asm volatile("ldmatrix.sync.aligned.m8n8.x2.shared.b16 {%0,%1}, [%2];"
        : "=r"(r[0]), "=r"(r[1]) : "r"(addr));
}
__device__ __forceinline__ void mma16816(float c[4], const uint32_t a[4], const uint32_t b[2]) {
    asm volatile("mma.sync.aligned.m16n8k16.row.col.f32.f16.f16.f32 "
        "{%0,%1,%2,%3},{%4,%5,%6,%7},{%8,%9},{%0,%1,%2,%3};"
        : "+f"(c[0]), "+f"(c[1]), "+f"(c[2]), "+f"(c[3])
        : "r"(a[0]), "r"(a[1]), "r"(a[2]), "r"(a[3]), "r"(b[0]), "r"(b[1]));
}
#define PBAR(id) asm volatile("bar.sync %0, 64;" :: "r"((id) + 1) : "memory")

// split v into fp16 hi + fp16 lo(residual); 2-byte stores
__device__ __forceinline__ void split_store2(char* bh, char* bl, uint32_t off, float v) {
    __half h = __float2half_rn(v);
    float r = v - __half2float(h);
    *(unsigned short*)(bh + off) = __half_as_ushort(h);
    *(unsigned short*)(bl + off) = __half_as_ushort(__float2half_rn(r));
}
// pack (v0,v1) -> hi word + lo word
__device__ __forceinline__ void split_pack2(float v0, float v1, uint32_t& hw, uint32_t& lw) {
    __half h0 = __float2half_rn(v0), h1 = __float2half_rn(v1);
    float r0 = v0 - __half2float(h0), r1 = v1 - __half2float(h1);
    hw = (uint32_t)__half_as_ushort(h0) | ((uint32_t)__half_as_ushort(h1) << 16);
    lw = (uint32_t)__half_as_ushort(__float2half_rn(r0))
       | ((uint32_t)__half_as_ushort(__float2half_rn(r1)) << 16);
}

// one layer: acc[8][4] += split-fp16 A[16 x K] * W[K x 64(nh half)]
template<int KSTEPS>
__device__ __forceinline__ void run_layer(uint32_t aH, uint32_t aL,
                                          uint32_t wH, uint32_t wL,
                                          int rowbase, int nh, int lane, float acc[8][4])
{
    const int arow = rowbase + (lane & 15);
    const int acol = (lane >> 4) * 8;
    const int lm   = lane & 15;
    const int brow = nh * 64 + (lm & 7);
    const int bcol = (lm >> 3) * 8;
#pragma unroll
    for (int s = 0; s < KSTEPS; s++) {
        const int kb = s >> 2, kk = (s & 3) * 16;
        uint32_t ah[4], al[4];
        uint32_t aoff = SWZ(arow * 128 + (kk + acol) * 2);
        ldsm_x4(aH + kb * 8192 + aoff, ah);
        ldsm_x4(aL + kb * 8192 + aoff, al);
#pragma unroll
        for (int nt = 0; nt < 8; nt++) {
            uint32_t woff = SWZ((brow + nt * 8) * 128 + (kk + bcol) * 2);
            uint32_t bh[2], bl[2];
            ldsm_x2(wH + kb * 16384 + woff, bh);
            ldsm_x2(wL + kb * 16384 + woff, bl);
            mma16816(acc[nt], ah, bh);
            mma16816(acc[nt], ah, bl);
            mma16816(acc[nt], al, bh);
        }
    }
}

// epilogue: bias + relu -> split fp16 -> swizzled act buffer
__device__ __forceinline__ void epi_store(char* sm_, uint32_t outH, uint32_t outL,
                                          const float* bias, float acc[8][4],
                                          int rowbase, int nh, int lane)
{
    const int r0 = rowbase + (lane >> 2);
    const int c0 = 2 * (lane & 3);
#pragma unroll
    for (int nt = 0; nt < 8; nt++) {
        int col = nh * 64 + nt * 8 + c0;
        float2 bb = *(const float2*)(bias + col);
        float v0 = fmaxf(acc[nt][0] + bb.x, 0.f);
        float v1 = fmaxf(acc[nt][1] + bb.y, 0.f);
        float v2 = fmaxf(acc[nt][2] + bb.x, 0.f);
        float v3 = fmaxf(acc[nt][3] + bb.y, 0.f);
        int kk = nt * 8 + c0;
        uint32_t off0 = SWZ(r0 * 128 + kk * 2);
        uint32_t off1 = SWZ((r0 + 8) * 128 + kk * 2);
        uint32_t hw, lw;
        split_pack2(v0, v1, hw, lw);
        *(uint32_t*)(sm_ + outH + nh * 8192 + off0) = hw;
        *(uint32_t*)(sm_ + outL + nh * 8192 + off0) = lw;
        split_pack2(v2, v3, hw, lw);
        *(uint32_t*)(sm_ + outH + nh * 8192 + off1) = hw;
        *(uint32_t*)(sm_ + outL + nh * 8192 + off1) = lw;
    }
}

__global__ void __launch_bounds__(256, 1)
enc_kernel(const float* __restrict__ points, const float* __restrict__ features,
           const int* __restrict__ batch_words,
           const float* __restrict__ w_ne, const float* __restrict__ b_ne,
           const float* __restrict__ w1, const float* __restrict__ b1,
           const float* __restrict__ w2, const float* __restrict__ b2,
           const float* __restrict__ w3, const float* __restrict__ b3,
           const float* __restrict__ wg1, const float* __restrict__ bg1,
           const float* __restrict__ wg2, const float* __restrict__ bg2,
           const float* __restrict__ wg3, const float* __restrict__ bg3,
           float* __restrict__ out)
{
    extern __shared__ char sm[];
    const int tid = threadIdx.x, lane = tid & 31, w = tid >> 5;
    const int pair = w >> 1, nh = w & 1;
    const int t64 = tid & 63;                     // thread within pair
    const uint32_t smb = smem_u32(sm);

    float* segp   = (float*)(sm + O_SEGP);
    int*   pooled = (int*)(sm + O_POOL);
    float* b2s    = (float*)(sm + O_B2);
    float* b3s    = (float*)(sm + O_B3);
    float* actf   = (float*)(sm + O_ACT);         // pass-1 / head scratch alias

    // ---- stage weights as split-fp16, transposed [o][k], SW128 k-blocks ----
    for (int idx = tid; idx < 8192; idx += 256) {          // W1 rows 32..95
        int k = idx >> 7, o = idx & 127;
        split_store2(sm + O_W1H, sm + O_W1L, SWZ(o * 128 + k * 2), w1[(32 + k) * 128 + o]);
    }
    for (int idx = tid; idx < 16384; idx += 256) {
        int k = idx >> 7, o = idx & 127;
        uint32_t off = (uint32_t)(k >> 6) * 16384 + SWZ(o * 128 + (k & 63) * 2);
        split_store2(sm + O_W2H, sm + O_W2L, off, w2[k * 128 + o]);
        split_store2(sm + O_W3H, sm + O_W3L, off, w3[k * 128 + o]);
    }
    if (tid < 128) { b2s[tid] = b2[tid]; b3s[tid] = b3[tid]; }
    __syncthreads();

    const int stride = (batch_words[NPTS - 1] == 0) ? 2 : 1;   // int64 vs int32
    const int rowbase = pair * 16;

    const int s0 = (blockIdx.x * BSEG) / NCTA;
    const int s1 = ((blockIdx.x + 1) * BSEG) / NCTA;

    for (int b = s0; b < s1; b++) {
        int lo, hi;
        {
            int l = 0, h = NPTS;
            while (l < h) { int m = (l + h) >> 1; if (batch_words[m * stride] < b) l = m + 1; else h = m; }
            lo = l; h = NPTS;
            while (l < h) { int m = (l + h) >> 1; if (batch_words[m * stride] < b + 1) l = m + 1; else h = m; }
            hi = l;
        }

        // ---- pass 1: encoder + segmax -> seg_part ----
        if (tid < 128) pooled[tid] = 0;
        if (tid < 96)  actf[tid] = w_ne[tid];
        if (tid < 32)  actf[96 + tid] = b_ne[tid];
        __syncthreads();
        {
            float em[32];
#pragma unroll
            for (int j = 0; j < 32; j++) em[j] = 0.f;
            const float* wne = actf; const float* bne = actf + 96;
            for (int n = lo + tid; n < hi; n += 256) {
                float x = points[3 * n], y = points[3 * n + 1], z = points[3 * n + 2];
#pragma unroll
                for (int j = 0; j < 32; j++)
                    em[j] = fmaxf(em[j], bne[j] + x * wne[j] + y * wne[32 + j] + z * wne[64 + j]);
            }
#pragma unroll
            for (int j = 0; j < 32; j++) {
#pragma unroll
                for (int o = 16; o > 0; o >>= 1)
                    em[j] = fmaxf(em[j], __shfl_xor_sync(0xFFFFFFFFu, em[j], o));
            }
            if (lane == 0) {
#pragma unroll
                for (int j = 0; j < 32; j++) actf[128 + w * 32 + j] = em[j];
            }
            __syncthreads();
            if (tid < 32) {
                float m = actf[128 + tid];
#pragma unroll
                for (int q = 1; q < 8; q++) m = fmaxf(m, actf[128 + q * 32 + tid]);
                actf[384 + tid] = m;
            }
            __syncthreads();
            if (tid < 128) {
                float s = b1[tid];
#pragma unroll
                for (int k = 0; k < 32; k++) s += actf[384 + k] * w1[k * 128 + tid];
                segp[tid] = s;
            }
            __syncthreads();
        }

        // ---- pass 2: pair-chunks of 16 pts through the MLP on tensor cores ----
        float rm[16];
#pragma unroll
        for (int j = 0; j < 16; j++) rm[j] = 0.f;

        const int pt = t64 >> 2, kq = (t64 & 3) * 16;
        float4 f[4];
        int n0 = lo + pair * 16;
#pragma unroll
        for (int i = 0; i < 4; i++) {
            int n = n0 + pt;
            f[i] = (n < hi) ? *(const float4*)(features + (size_t)n * 64 + kq + 4 * i)
                            : make_float4(0.f, 0.f, 0.f, 0.f);
        }

        for (; n0 < hi; n0 += 64) {
            // stage this chunk's features -> buf0 kb0 (hi/lo)
            {
                int row = rowbase + pt;
#pragma unroll
                for (int i = 0; i < 4; i++) {
                    int k = kq + 4 * i;
                    uint32_t o0 = SWZ(row * 128 + k * 2);
                    uint32_t o1 = SWZ(row * 128 + (k + 2) * 2);
                    uint32_t hw, lw;
                    split_pack2(f[i].x, f[i].y, hw, lw);
                    *(uint32_t*)(sm + O_ACT + o0) = hw;
                    *(uint32_t*)(sm + O_ACT + 16384 + o0) = lw;
                    split_pack2(f[i].z, f[i].w, hw, lw);
                    *(uint32_t*)(sm + O_ACT + o1) = hw;
                    *(uint32_t*)(sm + O_ACT + 16384 + o1) = lw;
                }
            }
            PBAR(pair);
            // prefetch next chunk
            {
                int nn = n0 + 64 + pt;
#pragma unroll
                for (int i = 0; i < 4; i++)
                    f[i] = (nn < hi) ? *(const float4*)(features + (size_t)nn * 64 + kq + 4 * i)
                                     : make_float4(0.f, 0.f, 0.f, 0.f);
            }

            float acc[8][4];
            // layer 1: K=64, in buf0, out buf1, bias = seg_part
#pragma unroll
            for (int nt = 0; nt < 8; nt++) { acc[nt][0] = acc[nt][1] = acc[nt][2] = acc[nt][3] = 0.f; }
            run_layer<4>(smb + O_ACT, smb + O_ACT + 16384, smb + O_W1H, smb + O_W1L,
                         rowbase, nh, lane, acc);
            epi_store(sm, O_ACT + 32768, O_ACT + 32768 + 16384, segp, acc, rowbase, nh, lane);
            PBAR(pair);

            // layer 2: K=128, in buf1, out buf0, bias = b2
#pragma unroll
            for (int nt = 0; nt < 8; nt++) { acc[nt][0] = acc[nt][1] = acc[nt][2] = acc[nt][3] = 0.f; }
            run_layer<8>(smb + O_ACT + 32768, smb + O_ACT + 32768 + 16384, smb + O_W2H, smb + O_W2L,
                         rowbase, nh, lane, acc);
            epi_store(sm, O_ACT, O_ACT + 16384, b2s, acc, rowbase, nh, lane);
            PBAR(pair);

            // layer 3: K=128, in buf0, bias = b3 -> masked running max (regs)
#pragma unroll
            for (int nt = 0; nt < 8; nt++) { acc[nt][0] = acc[nt][1] = acc[nt][2] = acc[nt][3] = 0.f; }
            run_layer<8>(smb + O_ACT, smb + O_ACT + 16384, smb + O_W3H, smb + O_W3L,
                         rowbase, nh, lane, acc);
            {
                const int r0 = lane >> 2;
                // FIX (R6): buffer row rowbase+r0 holds point n0 + r0 (n0 already
                // includes pair*16); previous code double-added rowbase.
                bool v0 = (n0 + r0) < hi;
                bool v1 = (n0 + r0 + 8) < hi;
#pragma unroll
                for (int nt = 0; nt < 8; nt++) {
                    int col = nh * 64 + nt * 8 + 2 * (lane & 3);
                    float2 bb = *(const float2*)(b3s + col);
                    if (v0) {
                        rm[2 * nt]     = fmaxf(rm[2 * nt],     acc[nt][0] + bb.x);
                        rm[2 * nt + 1] = fmaxf(rm[2 * nt + 1], acc[nt][1] + bb.y);
                    }
                    if (v1) {
                        rm[2 * nt]     = fmaxf(rm[2 * nt],     acc[nt][2] + bb.x);
                        rm[2 * nt + 1] = fmaxf(rm[2 * nt + 1], acc[nt][3] + bb.y);
                    }
                }
            }
            PBAR(pair);   // buf0 reads done before next staging
        }

        // reduce rm across lanes sharing the same column (stride-4 groups)
#pragma unroll
        for (int j = 0; j < 16; j++) {
#pragma unroll
            for (int o = 4; o < 32; o <<= 1)
                rm[j] = fmaxf(rm[j], __shfl_xor_sync(0xFFFFFFFFu, rm[j], o));
        }
        if (lane < 4) {
#pragma unroll
            for (int nt = 0; nt < 8; nt++) {
                atomicMax(&pooled[nh * 64 + nt * 8 + 2 * lane],     __float_as_int(rm[2 * nt]));
                atomicMax(&pooled[nh * 64 + nt * 8 + 2 * lane + 1], __float_as_int(rm[2 * nt + 1]));
            }
        }
        __syncthreads();

        // ---- pass 3: head MLP 128 -> 128 -> 64 -> 32 ----
        if (tid < 128) {
            float s = bg1[tid];
#pragma unroll 8
            for (int k = 0; k < 128; k++) s += __int_as_float(pooled[k]) * wg1[k * 128 + tid];
            actf[tid] = fmaxf(s, 0.f);
        }
        __syncthreads();
        if (tid < 64) {
            float s = bg2[tid];
#pragma unroll 8
            for (int k = 0; k < 128; k++) s += actf[k] * wg2[k * 64 + tid];
            actf[128 + tid] = fmaxf(s, 0.f);
        }
        __syncthreads();
        if (tid < 32) {
            float s = bg3[tid];
#pragma unroll 8
            for (int k = 0; k < 64; k++) s += actf[128 + k] * wg3[k * 32 + tid];
            out[b * 32 + tid] = fmaxf(s, 0.f);
        }
        __syncthreads();
    }
}

extern "C" void kernel_launch(void* const* d_in, const int* in_sizes, int n_in,
                              void* d_out, int out_size)
{
    const float* points   = (const float*)d_in[0];
    const float* features = (const float*)d_in[1];
    const int*   batchw   = (const int*)  d_in[2];
    const float* w_ne = (const float*)d_in[3];
    const float* b_ne = (const float*)d_in[4];
    const float* w1   = (const float*)d_in[5];
    const float* b1   = (const float*)d_in[6];
    const float* w2   = (const float*)d_in[7];
    const float* b2   = (const float*)d_in[8];
    const float* w3   = (const float*)d_in[9];
    const float* b3   = (const float*)d_in[10];
    const float* wg1  = (const float*)d_in[11];
    const float* bg1  = (const float*)d_in[12];
    const float* wg2  = (const float*)d_in[13];
    const float* bg2  = (const float*)d_in[14];
    const float* wg3  = (const float*)d_in[15];
    const float* bg3  = (const float*)d_in[16];
    float* out = (float*)d_out;

    cudaFuncSetAttribute(enc_kernel, cudaFuncAttributeMaxDynamicSharedMemorySize, SMEM_BYTES);
    enc_kernel<<<NCTA, 256, SMEM_BYTES>>>(
        points, features, batchw,
        w_ne, b_ne, w1, b1, w2, b2, w3, b3,
        wg1, bg1, wg2, bg2, wg3, bg3, out);
}